// round 7
// baseline (speedup 1.0000x reference)
#include <cuda_runtime.h>
#include <cuda_fp16.h>

#define B_  256
#define C_  1152
#define N_  10
#define ND_ 160          // N_*D_
#define CCH_ 144         // c-chunks of 8 in GEMM kernel

// u_hat scratch (fp16), layout in halfs: [b][c][g(0..1)][n(0..9)][8]
//   half offset = ((b*C_ + c)*160) + g*80 + n*8 + dd,  d = g*8 + dd
__device__ unsigned short g_uhat[(size_t)256*1152*160];
// per-c-chunk partial sums of u_hat over c: [cchunk(144)][b][p]  (p-layout g*80+n*8+dd)
__device__ float g_s0p[(size_t)CCH_*256*160];

// ---------------------------------------------------------------------------
// K1: u_hat[b,n,c,d] = sum_i W[n,c,d,i]*x[b,c,i]
// grid (144 c-chunks of 8, 4 b-chunks of 64), 320 threads:
// warp = n, lane>>3 = q (d-quarter), lane&7 = c_local. W in registers.
// ---------------------------------------------------------------------------
__global__ __launch_bounds__(320, 2) void k1_gemm(const float* __restrict__ x,
                                                  const float* __restrict__ W)
{
    const int t    = threadIdx.x;
    const int n    = t >> 5;          // warp id = output capsule
    const int lane = t & 31;
    const int q    = lane >> 3;       // d-quarter 0..3
    const int cl   = lane & 7;        // c within block
    const int c    = blockIdx.x * 8 + cl;
    const int b0   = blockIdx.y * 64;

    // W regs: Wr[dd*8+i] = W[n][c][q*4+dd][i]
    float Wr[32];
    {
        const float4* Wp = reinterpret_cast<const float4*>(
            W + ((size_t)(n*C_ + c))*128 + q*32);
#pragma unroll
        for (int k = 0; k < 8; ++k) {
            float4 f = Wp[k];
            Wr[4*k]=f.x; Wr[4*k+1]=f.y; Wr[4*k+2]=f.z; Wr[4*k+3]=f.w;
        }
    }

    // 4-deep x prefetch ring
    float4 xa[4], xb[4];
#pragma unroll
    for (int k = 0; k < 4; ++k) {
        const float* xp = x + ((size_t)(b0+k)*C_ + c)*8;
        xa[k] = *reinterpret_cast<const float4*>(xp);
        xb[k] = *reinterpret_cast<const float4*>(xp + 4);
    }

    // p-layout inner offset for this thread's 4 d's (d = q*4..q*4+3)
    const int  poff  = (q>>1)*80 + n*8 + (q&1)*4;
    const size_t ubase = (size_t)c*160 + poff;
    const size_t sbase = (size_t)blockIdx.x*(B_*ND_) + poff;

    for (int b = b0; b < b0 + 64; b += 4) {
#pragma unroll
        for (int k = 0; k < 4; ++k) {
            float xv[8];
            xv[0]=xa[k].x; xv[1]=xa[k].y; xv[2]=xa[k].z; xv[3]=xa[k].w;
            xv[4]=xb[k].x; xv[5]=xb[k].y; xv[6]=xb[k].z; xv[7]=xb[k].w;
            if (b + 4 + k < b0 + 64) {
                const float* xp = x + ((size_t)(b+4+k)*C_ + c)*8;
                xa[k] = *reinterpret_cast<const float4*>(xp);
                xb[k] = *reinterpret_cast<const float4*>(xp + 4);
            }

            float u[4];
#pragma unroll
            for (int dd = 0; dd < 4; ++dd) {
                float a = 0.f;
#pragma unroll
                for (int i = 0; i < 8; ++i) a = fmaf(Wr[dd*8+i], xv[i], a);
                u[dd] = a;
            }

            // store fp16 (8 bytes)
            __half2 h01 = __floats2half2_rn(u[0], u[1]);
            __half2 h23 = __floats2half2_rn(u[2], u[3]);
            uint2 val;
            val.x = *reinterpret_cast<unsigned int*>(&h01);
            val.y = *reinterpret_cast<unsigned int*>(&h23);
            *reinterpret_cast<uint2*>(g_uhat + (size_t)(b+k)*(C_*160) + ubase) = val;

            // per-chunk s0 partial: reduce over the 8 c lanes
            float p0=u[0], p1=u[1], p2=u[2], p3=u[3];
#pragma unroll
            for (int off = 1; off < 8; off <<= 1) {
                p0 += __shfl_xor_sync(0xffffffffu, p0, off);
                p1 += __shfl_xor_sync(0xffffffffu, p1, off);
                p2 += __shfl_xor_sync(0xffffffffu, p2, off);
                p3 += __shfl_xor_sync(0xffffffffu, p3, off);
            }
            if (cl == 0)
                *reinterpret_cast<float4*>(g_s0p + sbase + (size_t)(b+k)*ND_) =
                    make_float4(p0, p1, p2, p3);
        }
    }
}

// ---------------------------------------------------------------------------
// K2: full dynamic routing, one batch element per CTA.
// 512 threads = 16 warps. Lane = g*16+n: g = d-half (8 d's), n = capsule.
// Each warp handles one c per step; 72 steps per pass.
// ---------------------------------------------------------------------------
__device__ __forceinline__ void cvt8(const uint4& H, float* u)
{
    unsigned int r[4] = {H.x, H.y, H.z, H.w};
#pragma unroll
    for (int k = 0; k < 4; ++k) {
        __half2 h = *reinterpret_cast<__half2*>(&r[k]);
        float2 f = __half22float2(h);
        u[2*k] = f.x; u[2*k+1] = f.y;
    }
}

__global__ __launch_bounds__(512, 2) void k2_routing(float* __restrict__ out)
{
    __shared__ __half bsm[C_*N_];      // routing logits b1 (fp16, 23 KB)
    __shared__ float  sred[16*ND_];    // per-warp s partials / s0 partials
    __shared__ float  ssm[ND_];        // s, p-layout
    __shared__ float  vsm[ND_];        // v, p-layout
    __shared__ float  fsm[N_];

    const int  b = blockIdx.x;
    const int  t = threadIdx.x;
    const int  w = t >> 5;
    const int  l = t & 31;
    const int  g = l >> 4;             // d-half
    const int  n = l & 15;
    const bool act = (n < N_);
    const int  p = g*80 + n*8;         // this lane's p-layout base

    // ---- s0 = 0.1 * sum_c u_hat (reduce 144 GEMM partials, 3-way split) ----
    if (t < 480) {
        const int pos = t % ND_, grp = t / ND_;
        float a0=0.f, a1=0.f, a2=0.f, a3=0.f;
        const float* sp = g_s0p + (size_t)b*ND_ + pos;
#pragma unroll 4
        for (int cc = grp*48; cc < grp*48 + 48; cc += 4) {
            a0 += sp[(size_t)(cc+0)*(B_*ND_)];
            a1 += sp[(size_t)(cc+1)*(B_*ND_)];
            a2 += sp[(size_t)(cc+2)*(B_*ND_)];
            a3 += sp[(size_t)(cc+3)*(B_*ND_)];
        }
        sred[grp*ND_ + pos] = a0+a1+a2+a3;
    }
    __syncthreads();
    if (t < ND_) ssm[t] = (sred[t] + sred[ND_+t] + sred[2*ND_+t]) * 0.1f;
    __syncthreads();
    if (t < N_) {
        float sq = 0.f;
#pragma unroll
        for (int h = 0; h < 2; ++h)
#pragma unroll
            for (int dd = 0; dd < 8; ++dd) {
                float v = ssm[h*80 + t*8 + dd]; sq += v*v;
            }
        fsm[t] = sq / (1.f + sq) / (sqrtf(sq) + 1e-8f);
    }
    __syncthreads();
    if (t < ND_) vsm[t] = ssm[t] * fsm[(t % 80) >> 3];
    __syncthreads();

    const unsigned short* uh = g_uhat + (size_t)b*(C_*160) + p;

    for (int pass = 0; pass < 2; ++pass) {
        float vreg[8];
#pragma unroll
        for (int dd = 0; dd < 8; ++dd) vreg[dd] = act ? vsm[p + dd] : 0.f;

        float sacc[8];
#pragma unroll
        for (int dd = 0; dd < 8; ++dd) sacc[dd] = 0.f;

        uint4 P[4];
        if (act) {
#pragma unroll
            for (int k = 0; k < 4; ++k)
                P[k] = *reinterpret_cast<const uint4*>(uh + (size_t)(w + 16*k)*160);
        }

        for (int i = 0; i < 72; ++i) {
            uint4 X = P[i & 3];
            if (act && i + 4 < 72)
                P[i & 3] = *reinterpret_cast<const uint4*>(uh + (size_t)(w + 16*(i+4))*160);

            float u[8];
            cvt8(X, u);

            float uv0 = 0.f, uv1 = 0.f;
#pragma unroll
            for (int dd = 0; dd < 8; dd += 2) {
                uv0 = fmaf(u[dd],   vreg[dd],   uv0);
                uv1 = fmaf(u[dd+1], vreg[dd+1], uv1);
            }
            float uv = uv0 + uv1;
            uv += __shfl_xor_sync(0xffffffffu, uv, 16);   // combine d-halves

            const int c = 16*i + w;
            float logit;
            if (pass == 0) {
                logit = uv;
                if (g == 0 && act) bsm[c*N_ + n] = __float2half(uv);
            } else {
                logit = uv + (act ? __half2float(bsm[c*N_ + n]) : 0.f);
            }

            float e = act ? __expf(logit) : 0.f;
            float ssum = e;
#pragma unroll
            for (int o = 8; o; o >>= 1)
                ssum += __shfl_xor_sync(0xffffffffu, ssum, o);
            float coef = e * __fdividef(1.f, ssum);

#pragma unroll
            for (int dd = 0; dd < 8; ++dd) sacc[dd] = fmaf(coef, u[dd], sacc[dd]);
        }

        __syncthreads();
        if (act) {
#pragma unroll
            for (int dd = 0; dd < 8; ++dd) sred[w*ND_ + p + dd] = sacc[dd];
        }
        __syncthreads();
        if (t < ND_) {
            float a = 0.f;
#pragma unroll
            for (int k = 0; k < 16; ++k) a += sred[k*ND_ + t];
            ssm[t] = a;
        }
        __syncthreads();
        if (t < N_) {
            float sq = 0.f;
#pragma unroll
            for (int h = 0; h < 2; ++h)
#pragma unroll
                for (int dd = 0; dd < 8; ++dd) {
                    float v = ssm[h*80 + t*8 + dd]; sq += v*v;
                }
            fsm[t] = sq / (1.f + sq) / (sqrtf(sq) + 1e-8f);
        }
        __syncthreads();
        if (t < ND_) vsm[t] = ssm[t] * fsm[(t % 80) >> 3];
        __syncthreads();
    }

    // write out: vsm p-layout -> out [b][n][d], d = g*8+dd
    if (t < ND_) {
        const int gg = t / 80, r = t % 80, nn = r >> 3, dd = r & 7;
        out[(size_t)b*ND_ + nn*16 + gg*8 + dd] = vsm[t];
    }
}

// ---------------------------------------------------------------------------
extern "C" void kernel_launch(void* const* d_in, const int* in_sizes, int n_in,
                              void* d_out, int out_size)
{
    const float* x;
    const float* W;
    if (in_sizes[0] == B_*C_*8) { x = (const float*)d_in[0]; W = (const float*)d_in[1]; }
    else                        { x = (const float*)d_in[1]; W = (const float*)d_in[0]; }
    float* out = (float*)d_out;

    k1_gemm<<<dim3(CCH_, 4), 320>>>(x, W);
    k2_routing<<<B_, 512>>>(out);
}

// round 8
// speedup vs baseline: 1.0203x; 1.0203x over previous
#include <cuda_runtime.h>
#include <cuda_fp16.h>

#define B_  256
#define C_  1152
#define N_  10
#define ND_ 160          // N_*D_
#define CCH_ 144         // k1 c-chunks of 8
#define QCH_ 8           // routing c-chunks of 144

// u_hat scratch (fp16), per (b,c) p-layout: [g(0..1)][n(0..9)][8]; d = g*8+dd
__device__ unsigned short g_uhat[(size_t)256*1152*160];
// per-c-chunk partial sums of u_hat over c (plain [n*16+d]): [cchunk(144)][b][160]
__device__ float g_s0p[(size_t)CCH_*256*160];
// routing per-chunk partial s: [qchunk(8)][b][160] plain layout
__device__ float g_sp[(size_t)QCH_*256*160];
// current v per b, plain layout
__device__ float g_v[(size_t)256*160];
// b1 logits fp16: [b][c][n]
__device__ unsigned short g_b1[(size_t)256*1152*10];

// ---------------------------------------------------------------------------
// K1: u_hat[b,n,c,d] = sum_i W[n,c,d,i]*x[b,c,i]
// grid (144 c-chunks of 8, 4 b-chunks of 64), 320 threads:
// warp = n, lane>>3 = q (d-quarter), lane&7 = c_local. W in regs, x staged in smem.
// ---------------------------------------------------------------------------
__global__ __launch_bounds__(320, 3) void k1_gemm(const float* __restrict__ x,
                                                  const float* __restrict__ W)
{
    __shared__ float xs[64*64];       // x[b_local][c_local*8+i], 16 KB

    const int t    = threadIdx.x;
    const int n    = t >> 5;          // warp id = output capsule
    const int lane = t & 31;
    const int q    = lane >> 3;       // d-quarter 0..3
    const int cl   = lane & 7;        // c within block
    const int c    = blockIdx.x * 8 + cl;
    const int b0   = blockIdx.y * 64;

    // W regs: Wr[dd*8+i] = W[n][c][q*4+dd][i]
    float Wr[32];
    {
        const float4* Wp = reinterpret_cast<const float4*>(
            W + ((size_t)(n*C_ + c))*128 + q*32);
#pragma unroll
        for (int k = 0; k < 8; ++k) {
            float4 f = Wp[k];
            Wr[4*k]=f.x; Wr[4*k+1]=f.y; Wr[4*k+2]=f.z; Wr[4*k+3]=f.w;
        }
    }

    // cooperative x stage: 64 b's x 64 floats (8 c x 8 i), contiguous per b
    for (int idx = t; idx < 1024; idx += 320) {
        int bl = idx >> 4;            // 16 float4 per b
        int r  = idx & 15;
        reinterpret_cast<float4*>(xs)[bl*16 + r] =
            reinterpret_cast<const float4*>(
                x + (size_t)(b0 + bl)*(C_*8) + blockIdx.x*64)[r];
    }
    __syncthreads();

    // p-layout inner offset for this thread's 4 d's (d = q*4..q*4+3)
    const size_t ubase = (size_t)c*160 + (size_t)(q>>1)*80 + n*8 + (q&1)*4;
    const size_t sbase = (size_t)blockIdx.x*(B_*ND_) + n*16 + q*4;   // plain layout

#pragma unroll 2
    for (int bl = 0; bl < 64; ++bl) {
        const int b = b0 + bl;
        const float4* xr = reinterpret_cast<const float4*>(xs + bl*64 + cl*8);
        float4 f0 = xr[0], f1 = xr[1];
        float xv[8];
        xv[0]=f0.x; xv[1]=f0.y; xv[2]=f0.z; xv[3]=f0.w;
        xv[4]=f1.x; xv[5]=f1.y; xv[6]=f1.z; xv[7]=f1.w;

        float u[4];
#pragma unroll
        for (int dd = 0; dd < 4; ++dd) {
            float a = 0.f;
#pragma unroll
            for (int i = 0; i < 8; ++i) a = fmaf(Wr[dd*8+i], xv[i], a);
            u[dd] = a;
        }

        // store fp16 (8 bytes)
        __half2 h01 = __floats2half2_rn(u[0], u[1]);
        __half2 h23 = __floats2half2_rn(u[2], u[3]);
        uint2 val;
        val.x = *reinterpret_cast<unsigned int*>(&h01);
        val.y = *reinterpret_cast<unsigned int*>(&h23);
        *reinterpret_cast<uint2*>(g_uhat + (size_t)b*(C_*160) + ubase) = val;

        // per-chunk s0 partial: reduce over the 8 c lanes
        float p0=u[0], p1=u[1], p2=u[2], p3=u[3];
#pragma unroll
        for (int off = 1; off < 8; off <<= 1) {
            p0 += __shfl_xor_sync(0xffffffffu, p0, off);
            p1 += __shfl_xor_sync(0xffffffffu, p1, off);
            p2 += __shfl_xor_sync(0xffffffffu, p2, off);
            p3 += __shfl_xor_sync(0xffffffffu, p3, off);
        }
        if (cl == 0)
            *reinterpret_cast<float4*>(g_s0p + sbase + (size_t)b*ND_) =
                make_float4(p0, p1, p2, p3);
    }
}

// ---------------------------------------------------------------------------
// K_red: sum partial s over chunks, squash -> v (or final output).
// grid 256 (b), 160 threads (t = n*16+d plain layout).
// which_in: 0 = g_s0p (nchunks chunks), 1 = g_sp.
// ---------------------------------------------------------------------------
__global__ __launch_bounds__(160) void k_red(int nchunks, float scale,
                                             int which_in, float* __restrict__ outp)
{
    const int b = blockIdx.x;
    const int t = threadIdx.x;
    const float* in = which_in ? g_sp : g_s0p;

    float s = 0.f;
#pragma unroll 4
    for (int k = 0; k < nchunks; ++k)
        s += in[((size_t)k*B_ + b)*ND_ + t];
    s *= scale;

    float sq = s*s;
#pragma unroll
    for (int o = 1; o < 16; o <<= 1)
        sq += __shfl_xor_sync(0xffffffffu, sq, o);   // sum over 16 d's (n-group)
    float f = sq / (1.f + sq) / (sqrtf(sq) + 1e-8f);
    float v = s * f;

    if (outp) outp[(size_t)b*ND_ + t] = v;
    else      g_v[(size_t)b*ND_ + t]  = v;
}

// ---------------------------------------------------------------------------
// K2 pass: one routing iteration over a 144-c chunk.
// grid (8 qchunks, 256 b), 256 threads = 8 warps.
// lane = g*16+n: g = c-parity (warp covers 2 c/step), n = capsule; 9 steps.
// PASS 1: logit = u.v1, store b1.   PASS 2: logit = b1 + u.v2.
// ---------------------------------------------------------------------------
__device__ __forceinline__ void cvt8(const uint4& H, float* u)
{
    unsigned int r[4] = {H.x, H.y, H.z, H.w};
#pragma unroll
    for (int k = 0; k < 4; ++k) {
        __half2 h = *reinterpret_cast<__half2*>(&r[k]);
        float2 f = __half22float2(h);
        u[2*k] = f.x; u[2*k+1] = f.y;
    }
}

template<int PASS>
__global__ __launch_bounds__(256, 3) void k2_pass()
{
    __shared__ float sred[8*ND_];

    const int  qc = blockIdx.x;       // c-chunk 0..7
    const int  b  = blockIdx.y;
    const int  t  = threadIdx.x;
    const int  w  = t >> 5;
    const int  l  = t & 31;
    const int  g  = l >> 4;
    const int  n  = l & 15;
    const bool act = (n < N_);

    float vreg[16];
    {
        const float4* vp = reinterpret_cast<const float4*>(g_v + (size_t)b*ND_ + n*16);
#pragma unroll
        for (int k = 0; k < 4; ++k) {
            float4 f = act ? vp[k] : make_float4(0.f,0.f,0.f,0.f);
            vreg[4*k]=f.x; vreg[4*k+1]=f.y; vreg[4*k+2]=f.z; vreg[4*k+3]=f.w;
        }
    }

    float sacc[16];
#pragma unroll
    for (int d = 0; d < 16; ++d) sacc[d] = 0.f;

    const unsigned short* uh = g_uhat + (size_t)b*(C_*160);
    int c = qc*144 + 2*w + g;

    uint4 A0, A1;
    float bcur = 0.f;
    if (act) {
        const unsigned short* p = uh + (size_t)c*160 + n*8;
        A0 = *reinterpret_cast<const uint4*>(p);
        A1 = *reinterpret_cast<const uint4*>(p + 80);
        if (PASS == 2) bcur = __half2float(
            *reinterpret_cast<const __half*>(g_b1 + ((size_t)b*C_ + c)*10 + n));
    }

#pragma unroll
    for (int i = 0; i < 9; ++i) {
        uint4 a0 = A0, a1 = A1;
        float bl_ = bcur;
        if (act && i < 8) {
            const unsigned short* p = uh + (size_t)(c+16)*160 + n*8;
            A0 = *reinterpret_cast<const uint4*>(p);
            A1 = *reinterpret_cast<const uint4*>(p + 80);
            if (PASS == 2) bcur = __half2float(
                *reinterpret_cast<const __half*>(g_b1 + ((size_t)b*C_ + c + 16)*10 + n));
        }

        float u[16];
        cvt8(a0, u);
        cvt8(a1, u + 8);

        float uv0 = 0.f, uv1 = 0.f;
#pragma unroll
        for (int d = 0; d < 16; d += 2) {
            uv0 = fmaf(u[d],   vreg[d],   uv0);
            uv1 = fmaf(u[d+1], vreg[d+1], uv1);
        }
        float uv = uv0 + uv1;

        float logit;
        if (PASS == 1) {
            logit = uv;
            if (act)
                *reinterpret_cast<__half*>(g_b1 + ((size_t)b*C_ + c)*10 + n) =
                    __float2half(uv);
        } else {
            logit = uv + bl_;
        }

        float e = act ? __expf(logit) : 0.f;
        float ssum = e;
#pragma unroll
        for (int o = 8; o; o >>= 1)
            ssum += __shfl_xor_sync(0xffffffffu, ssum, o);
        float coef = e * __fdividef(1.f, ssum);

#pragma unroll
        for (int d = 0; d < 16; ++d) sacc[d] = fmaf(coef, u[d], sacc[d]);

        c += 16;
    }

    // combine the two c-parity halves of each warp
#pragma unroll
    for (int d = 0; d < 16; ++d)
        sacc[d] += __shfl_xor_sync(0xffffffffu, sacc[d], 16);

    if (g == 0 && act) {
#pragma unroll
        for (int d = 0; d < 16; ++d) sred[w*ND_ + n*16 + d] = sacc[d];
    }
    __syncthreads();
    if (t < ND_) {
        float a = 0.f;
#pragma unroll
        for (int k = 0; k < 8; ++k) a += sred[k*ND_ + t];
        g_sp[((size_t)qc*B_ + b)*ND_ + t] = a;
    }
}

// ---------------------------------------------------------------------------
extern "C" void kernel_launch(void* const* d_in, const int* in_sizes, int n_in,
                              void* d_out, int out_size)
{
    const float* x;
    const float* W;
    if (in_sizes[0] == B_*C_*8) { x = (const float*)d_in[0]; W = (const float*)d_in[1]; }
    else                        { x = (const float*)d_in[1]; W = (const float*)d_in[0]; }
    float* out = (float*)d_out;

    k1_gemm<<<dim3(CCH_, 4), 320>>>(x, W);
    k_red<<<B_, 160>>>(CCH_, 0.1f, 0, nullptr);        // s0 -> v1
    k2_pass<1><<<dim3(QCH_, B_), 256>>>();             // pass 1: b1, partial s
    k_red<<<B_, 160>>>(QCH_, 1.0f, 1, nullptr);        // -> v2
    k2_pass<2><<<dim3(QCH_, B_), 256>>>();             // pass 2: b2 logits, partial s
    k_red<<<B_, 160>>>(QCH_, 1.0f, 1, out);            // -> v3 = output
}